// round 7
// baseline (speedup 1.0000x reference)
#include <cuda_runtime.h>
#include <cuda_bf16.h>
#include <math.h>

// ---------------- static problem config ----------------
#define BB   64
#define LLEN 1024
#define CIN  16
#define DD   256
#define HH   8
#define DFF  1024
#define HSZ  256
#define NLAY 2
#define TOPK 20
#define MAW  25   // moving average window

// ---------------- device scratch (no allocs allowed) ----------------
__device__ __align__(16) float g_h1 [BB*LLEN*DD];            // conv1 out
__device__ __align__(16) float g_enc[BB*LLEN*DD];            // encoder state
__device__ __align__(16) float g_q  [BB*LLEN*DD];
__device__ __align__(16) float g_k  [BB*LLEN*DD];
__device__ __align__(16) float g_v  [BB*LLEN*DD];
__device__ __align__(16) float g_ac [BB*LLEN*DD];            // autocorr agg out
__device__ __align__(16) float g_xs [BB*LLEN*DD];            // x (pre-decomp) / conv2 out
__device__ __align__(16) float g_xd [BB*LLEN*DD];            // x after decomp
__device__ __align__(16) float g_big[BB*LLEN*DFF];           // FFN hidden
__device__ __align__(16) float g_rp [BB*LLEN];               // correlation sums per tau
__device__ int   g_del[BB*TOPK];
__device__ float g_w  [BB*TOPK];
__device__ __align__(16) float g_emb[BB*HSZ];
__device__ __align__(16) float g_final[BB*(NLAY*DD+HSZ)];    // [64][768]
__device__ __align__(16) float g_o1[BB*HSZ];
__device__ __align__(16) float g_o2[BB*HSZ];
__device__ __align__(16) float g_w2t[768*256];               // conv2 weights as [K=768][N=256]

// ---------------- epilogue flags ----------------
#define EPI_BIAS 1
#define EPI_RELU 2
#define EPI_GELU 4
#define EPI_RES  8
#define EPI_GRAM 16   // no C tile write; reduce wrapped diagonals into C (=rp+b*1024)

__device__ __forceinline__ unsigned f2tf(float f) {
    unsigned u;
    asm("cvt.rna.tf32.f32 %0, %1;" : "=r"(u) : "f"(f));
    return u;
}

__device__ __forceinline__ void mma_tf32(float* c, const unsigned* a, const unsigned* b) {
    asm volatile(
        "mma.sync.aligned.m16n8k8.row.col.f32.tf32.tf32.f32 "
        "{%0,%1,%2,%3}, {%4,%5,%6,%7}, {%8,%9}, {%0,%1,%2,%3};\n"
        : "+f"(c[0]), "+f"(c[1]), "+f"(c[2]), "+f"(c[3])
        : "r"(a[0]), "r"(a[1]), "r"(a[2]), "r"(a[3]), "r"(b[0]), "r"(b[1]));
}

// =====================================================================
// tf32 tensor-core GEMM, 128x128x16 tile, 256 threads (8 warps),
// warp tile 64x32 (warps arranged 2 x 4), mma m16n8k8.
// Register-prefetch of next K-tile overlaps global loads with mma phase.
// AMODE: 0 = normal A [M,K]; 1 = conv2 shifted-A (A is h1[L,256], K=768,
//        k-chunk j in {0,1,2} reads row l+j-1 with zero padding).
// TB: false -> B[K,N] row-major; true -> B[N,K] row-major.
// Batched via gridDim.z with element strides sA,sB,sC.
// EPI_GRAM: instead of writing C[M,N], reduce tile into wrapped-diagonal
//           sums: C[(m-n)&1023] += acc  (C is rp + b*1024, pre-zeroed).
// =====================================================================
template<int AMODE, bool TB, int EPI>
__global__ __launch_bounds__(256) void tgemm128(
    const float* __restrict__ A, const float* __restrict__ B,
    const float* __restrict__ bias, const float* __restrict__ res,
    float* __restrict__ C, int M, int N, int K,
    long long sA, long long sB, long long sC)
{
    __shared__ unsigned As[16][136];   // stride 136: conflict-free fragment reads
    __shared__ unsigned Bs[16][136];
    __shared__ float sdiag[256];
    long long bz = blockIdx.z;
    A += bz * sA;  B += bz * sB;  C += bz * sC;
    if (EPI & EPI_RES) res += bz * sC;

    int m0 = blockIdx.y * 128, n0 = blockIdx.x * 128;
    int t = threadIdx.x;
    int wid = t >> 5, lane = t & 31;
    int g = lane >> 2, t4 = lane & 3;
    int wm = (wid & 1) * 64;
    int wn = (wid >> 1) * 32;

    float acc[4][4][4];
    #pragma unroll
    for (int mi = 0; mi < 4; mi++)
        #pragma unroll
        for (int ni = 0; ni < 4; ni++)
            #pragma unroll
            for (int r = 0; r < 4; r++) acc[mi][ni][r] = 0.f;

    const int am = t >> 1, ak = (t & 1) * 8;
    int bn, bk;
    if (TB) { bn = t >> 1;  bk = (t & 1) * 8; }
    else    { bk = t >> 4;  bn = (t & 15) * 8; }

    float avr[8], bvr[8];

#define LOAD_TILES(K0)                                                        \
    {                                                                         \
        if (AMODE == 0) {                                                     \
            const float* ap = A + (long long)(m0 + am) * K + (K0) + ak;       \
            float4 w0 = *(const float4*)ap;                                   \
            float4 w1 = *(const float4*)(ap + 4);                             \
            avr[0]=w0.x; avr[1]=w0.y; avr[2]=w0.z; avr[3]=w0.w;               \
            avr[4]=w1.x; avr[5]=w1.y; avr[6]=w1.z; avr[7]=w1.w;               \
        } else {                                                              \
            int kk = (K0) + ak;                                               \
            int sft = kk >> 8;                                                \
            int cc  = kk & 255;                                               \
            int ll  = m0 + am + sft - 1;                                      \
            if (ll >= 0 && ll < LLEN) {                                       \
                const float* ap = A + (long long)ll * 256 + cc;               \
                float4 w0 = *(const float4*)ap;                               \
                float4 w1 = *(const float4*)(ap + 4);                         \
                avr[0]=w0.x; avr[1]=w0.y; avr[2]=w0.z; avr[3]=w0.w;           \
                avr[4]=w1.x; avr[5]=w1.y; avr[6]=w1.z; avr[7]=w1.w;           \
            } else {                                                          \
                _Pragma("unroll")                                             \
                for (int j = 0; j < 8; j++) avr[j] = 0.f;                     \
            }                                                                 \
        }                                                                     \
        if (TB) {                                                             \
            const float* bp = B + (long long)(n0 + bn) * K + (K0) + bk;       \
            float4 w0 = *(const float4*)bp;                                   \
            float4 w1 = *(const float4*)(bp + 4);                             \
            bvr[0]=w0.x; bvr[1]=w0.y; bvr[2]=w0.z; bvr[3]=w0.w;               \
            bvr[4]=w1.x; bvr[5]=w1.y; bvr[6]=w1.z; bvr[7]=w1.w;               \
        } else {                                                              \
            const float* bp = B + (long long)((K0) + bk) * N + n0 + bn;       \
            float4 w0 = *(const float4*)bp;                                   \
            float4 w1 = *(const float4*)(bp + 4);                             \
            bvr[0]=w0.x; bvr[1]=w0.y; bvr[2]=w0.z; bvr[3]=w0.w;               \
            bvr[4]=w1.x; bvr[5]=w1.y; bvr[6]=w1.z; bvr[7]=w1.w;               \
        }                                                                     \
    }

    LOAD_TILES(0);

    for (int k0 = 0; k0 < K; k0 += 16) {
        // store staged tile to smem (with tf32 rounding)
        #pragma unroll
        for (int j = 0; j < 8; j++) As[ak + j][am] = f2tf(avr[j]);
        if (TB) {
            #pragma unroll
            for (int j = 0; j < 8; j++) Bs[bk + j][bn] = f2tf(bvr[j]);
        } else {
            #pragma unroll
            for (int j = 0; j < 8; j++) Bs[bk][bn + j] = f2tf(bvr[j]);
        }
        __syncthreads();

        // prefetch next tile while mma runs
        if (k0 + 16 < K) LOAD_TILES(k0 + 16);

        #pragma unroll
        for (int ks = 0; ks < 2; ks++) {
            unsigned afr[4][4], bfr[4][2];
            #pragma unroll
            for (int mi = 0; mi < 4; mi++) {
                int mr = wm + mi * 16 + g;
                afr[mi][0] = As[ks * 8 + t4][mr];
                afr[mi][1] = As[ks * 8 + t4][mr + 8];
                afr[mi][2] = As[ks * 8 + t4 + 4][mr];
                afr[mi][3] = As[ks * 8 + t4 + 4][mr + 8];
            }
            #pragma unroll
            for (int ni = 0; ni < 4; ni++) {
                int nc = wn + ni * 8 + g;
                bfr[ni][0] = Bs[ks * 8 + t4][nc];
                bfr[ni][1] = Bs[ks * 8 + t4 + 4][nc];
            }
            #pragma unroll
            for (int mi = 0; mi < 4; mi++)
                #pragma unroll
                for (int ni = 0; ni < 4; ni++)
                    mma_tf32(acc[mi][ni], afr[mi], bfr[ni]);
        }
        __syncthreads();
    }
#undef LOAD_TILES

    if (EPI & EPI_GRAM) {
        // wrapped-diagonal reduction of this 128x128 tile into tau bins.
        sdiag[t] = 0.f;
        __syncthreads();
        #pragma unroll
        for (int mi = 0; mi < 4; mi++) {
            #pragma unroll
            for (int ni = 0; ni < 4; ni++) {
                int li0 = wm + mi * 16 + g;
                int lj0 = wn + ni * 8 + t4 * 2;
                #pragma unroll
                for (int half = 0; half < 2; half++) {
                    int li = li0 + half * 8;
                    atomicAdd(&sdiag[li - lj0 + 127],     acc[mi][ni][half * 2 + 0]);
                    atomicAdd(&sdiag[li - (lj0+1) + 127], acc[mi][ni][half * 2 + 1]);
                }
            }
        }
        __syncthreads();
        if (t < 255) {
            int tau = (m0 - n0 - 127 + t) & (LLEN - 1);
            atomicAdd(&C[tau], sdiag[t]);
        }
        return;
    }

    #pragma unroll
    for (int mi = 0; mi < 4; mi++) {
        #pragma unroll
        for (int ni = 0; ni < 4; ni++) {
            long long row0 = m0 + wm + mi * 16 + g;
            int col0 = n0 + wn + ni * 8 + t4 * 2;
            #pragma unroll
            for (int half = 0; half < 2; half++) {
                long long gm = row0 + half * 8;
                float v0 = acc[mi][ni][half * 2 + 0];
                float v1 = acc[mi][ni][half * 2 + 1];
                if (EPI & EPI_BIAS) { v0 += bias[col0]; v1 += bias[col0 + 1]; }
                if (EPI & EPI_RELU) { v0 = fmaxf(v0, 0.f); v1 = fmaxf(v1, 0.f); }
                if (EPI & EPI_GELU) {
                    v0 = 0.5f * v0 * (1.f + erff(v0 * 0.70710678118654752f));
                    v1 = 0.5f * v1 * (1.f + erff(v1 * 0.70710678118654752f));
                }
                if (EPI & EPI_RES) {
                    v0 += res[gm * N + col0];
                    v1 += res[gm * N + col0 + 1];
                }
                *(float2*)(C + gm * N + col0) = make_float2(v0, v1);
            }
        }
    }
}

// transpose conv2 weights [D=256][C=256][3] -> [K=768 (j*256+c)][D=256]
__global__ void w2t_kernel(const float* __restrict__ w, float* __restrict__ o)
{
    int i = blockIdx.x * 256 + threadIdx.x;
    int d  = i & 255;
    int kk = i >> 8;
    int c  = kk & 255;
    int j  = kk >> 8;
    o[(long long)kk * 256 + d] = w[(long long)d * 768 + c * 3 + j];
}

// 64x64x16 fp32 tile version for small-M GEMMs (M=64). B is [K,N] only.
template<int EPI>
__global__ __launch_bounds__(256) void sgemm64(
    const float* __restrict__ A, const float* __restrict__ B,
    const float* __restrict__ bias, float* __restrict__ C,
    int M, int N, int K)
{
    __shared__ float As[16][64];
    __shared__ float Bs[16][64];
    int m0 = blockIdx.y * 64, n0 = blockIdx.x * 64;
    int t = threadIdx.x;
    int tx = t & 15, ty = t >> 4;
    float acc[4][4];
    #pragma unroll
    for (int i = 0; i < 4; i++)
        #pragma unroll
        for (int j = 0; j < 4; j++) acc[i][j] = 0.f;

    const int am = t >> 2, ak = (t & 3) * 4;
    const int bk = t >> 4, bn = (t & 15) * 4;

    for (int k0 = 0; k0 < K; k0 += 16) {
        float4 av = *(const float4*)(A + (long long)(m0 + am) * K + k0 + ak);
        As[ak + 0][am] = av.x; As[ak + 1][am] = av.y;
        As[ak + 2][am] = av.z; As[ak + 3][am] = av.w;
        *(float4*)&Bs[bk][bn] = *(const float4*)(B + (long long)(k0 + bk) * N + n0 + bn);
        __syncthreads();
        #pragma unroll
        for (int kk = 0; kk < 16; kk++) {
            float4 a4 = *(const float4*)&As[kk][ty * 4];
            float4 b4 = *(const float4*)&Bs[kk][tx * 4];
            float a[4] = {a4.x, a4.y, a4.z, a4.w};
            float b[4] = {b4.x, b4.y, b4.z, b4.w};
            #pragma unroll
            for (int i = 0; i < 4; i++)
                #pragma unroll
                for (int j = 0; j < 4; j++)
                    acc[i][j] += a[i] * b[j];
        }
        __syncthreads();
    }
    #pragma unroll
    for (int i = 0; i < 4; i++) {
        long long gm = m0 + ty * 4 + i;
        float vr[4];
        #pragma unroll
        for (int j = 0; j < 4; j++) {
            int gn = n0 + tx * 4 + j;
            float v = acc[i][j];
            if (EPI & EPI_BIAS) v += bias[gn];
            if (EPI & EPI_RELU) v = fmaxf(v, 0.f);
            vr[j] = v;
        }
        *(float4*)(C + gm * N + n0 + tx * 4) = make_float4(vr[0], vr[1], vr[2], vr[3]);
    }
}

// =====================================================================
// conv1: [B,L,16] -> relu(conv1d k=3 pad=1) -> [B,L,256]
// =====================================================================
__global__ __launch_bounds__(256) void conv1_kernel(
    const float* __restrict__ x, const float* __restrict__ w,
    const float* __restrict__ bias, float* __restrict__ out)
{
    int l = blockIdx.x, b = blockIdx.y, d = threadIdx.x;
    __shared__ float sx[3][16];
    if (d < 48) {
        int j = d / 16, c = d % 16;
        int ll = l + j - 1;
        sx[j][c] = (ll >= 0 && ll < LLEN) ? x[((long long)b * LLEN + ll) * CIN + c] : 0.f;
    }
    __syncthreads();
    float acc = bias[d];
    const float* wd = w + d * 48;
    #pragma unroll
    for (int c = 0; c < 16; c++)
        #pragma unroll
        for (int j = 0; j < 3; j++)
            acc += sx[j][c] * wd[c * 3 + j];
    out[((long long)b * LLEN + l) * DD + d] = fmaxf(acc, 0.f);
}

// =====================================================================
// LayerNorm over last dim = 256. 8 rows/block, 32 lanes/row, shuffle.
// =====================================================================
__global__ __launch_bounds__(256) void ln256_kernel(
    const float* __restrict__ in, const float* __restrict__ g,
    const float* __restrict__ bt, float* __restrict__ out,
    long long ostride, long long ooff)
{
    int t = threadIdx.x;
    int lane = t & 31, wr = t >> 5;
    long long r = (long long)blockIdx.x * 8 + wr;
    const float* ip = in + r * 256 + lane * 8;
    float4 v0 = *(const float4*)ip;
    float4 v1 = *(const float4*)(ip + 4);
    float x[8] = {v0.x, v0.y, v0.z, v0.w, v1.x, v1.y, v1.z, v1.w};
    float s = 0.f;
    #pragma unroll
    for (int j = 0; j < 8; j++) s += x[j];
    #pragma unroll
    for (int o = 16; o; o >>= 1) s += __shfl_xor_sync(0xFFFFFFFFu, s, o);
    float mean = s * (1.f / 256.f);
    float vs = 0.f;
    #pragma unroll
    for (int j = 0; j < 8; j++) { x[j] -= mean; vs += x[j] * x[j]; }
    #pragma unroll
    for (int o = 16; o; o >>= 1) vs += __shfl_xor_sync(0xFFFFFFFFu, vs, o);
    float inv = rsqrtf(vs * (1.f / 256.f) + 1e-5f);
    float4 g0 = *(const float4*)(g + lane * 8);
    float4 g1 = *(const float4*)(g + lane * 8 + 4);
    float4 b0 = *(const float4*)(bt + lane * 8);
    float4 b1 = *(const float4*)(bt + lane * 8 + 4);
    float gg[8] = {g0.x, g0.y, g0.z, g0.w, g1.x, g1.y, g1.z, g1.w};
    float bb[8] = {b0.x, b0.y, b0.z, b0.w, b1.x, b1.y, b1.z, b1.w};
    float o8[8];
    #pragma unroll
    for (int j = 0; j < 8; j++) o8[j] = x[j] * inv * gg[j] + bb[j];
    float* op = out + r * ostride + ooff + lane * 8;
    *(float4*)op       = make_float4(o8[0], o8[1], o8[2], o8[3]);
    *(float4*)(op + 4) = make_float4(o8[4], o8[5], o8[6], o8[7]);
}

// =====================================================================
// top-k(20) + softmax (ties -> lowest index, matches lax.top_k)
// reads rp[b][tau] (raw sums; mean = sum/256)
// =====================================================================
__global__ __launch_bounds__(256) void topk_kernel(
    const float* __restrict__ rp, int* __restrict__ del, float* __restrict__ wts)
{
    int b = blockIdx.x, t = threadIdx.x;
    __shared__ float sv[LLEN];
    __shared__ float rv[256];
    __shared__ int   ri[256];
    __shared__ float selv[TOPK];
    __shared__ int   seli[TOPK];
    for (int i = t; i < LLEN; i += 256)
        sv[i] = rp[(long long)b * LLEN + i] * (1.f / 256.f);
    __syncthreads();
    for (int iter = 0; iter < TOPK; iter++) {
        float bv = -INFINITY; int bi = 1 << 30;
        for (int i = t; i < LLEN; i += 256) {
            float v = sv[i];
            if (v > bv || (v == bv && i < bi)) { bv = v; bi = i; }
        }
        rv[t] = bv; ri[t] = bi; __syncthreads();
        for (int s = 128; s > 0; s >>= 1) {
            if (t < s) {
                if (rv[t + s] > rv[t] || (rv[t + s] == rv[t] && ri[t + s] < ri[t])) {
                    rv[t] = rv[t + s]; ri[t] = ri[t + s];
                }
            }
            __syncthreads();
        }
        if (t == 0) { selv[iter] = rv[0]; seli[iter] = ri[0]; sv[ri[0]] = -INFINITY; }
        __syncthreads();
    }
    if (t == 0) {
        float m = selv[0];
        float e[TOPK], ssum = 0.f;
        for (int k2 = 0; k2 < TOPK; k2++) { e[k2] = expf(selv[k2] - m); ssum += e[k2]; }
        float inv = 1.f / ssum;
        for (int k2 = 0; k2 < TOPK; k2++) {
            wts[b * TOPK + k2] = e[k2] * inv;
            del[b * TOPK + k2] = seli[k2];
        }
    }
}

// =====================================================================
// delayed aggregation: out[b,l,d] = sum_k w[k] * V[b,(l+delay[k])%L,d]
// =====================================================================
__global__ __launch_bounds__(256) void agg_kernel(
    const float* __restrict__ V, const int* __restrict__ del,
    const float* __restrict__ wts, float* __restrict__ out)
{
    int l = blockIdx.x, b = blockIdx.y, d = threadIdx.x;
    __shared__ int   sd[TOPK];
    __shared__ float sw[TOPK];
    if (d < TOPK) { sd[d] = del[b * TOPK + d]; sw[d] = wts[b * TOPK + d]; }
    __syncthreads();
    const float* vb = V + (long long)b * LLEN * DD;
    float acc = 0.f;
    #pragma unroll
    for (int k2 = 0; k2 < TOPK; k2++)
        acc += sw[k2] * vb[(long long)((l + sd[k2]) & (LLEN - 1)) * DD + d];
    out[((long long)b * LLEN + l) * DD + d] = acc;
}

// =====================================================================
// series decomposition: out = in - movavg25(in, replicate-pad)
// =====================================================================
__global__ __launch_bounds__(256) void decomp_kernel(
    const float* __restrict__ in, float* __restrict__ out)
{
    __shared__ float s[88][65];
    int b  = blockIdx.z;
    int c0 = blockIdx.y * 64;
    int l0 = blockIdx.x * 64;
    int t  = threadIdx.x;
    const float* base = in + (long long)b * LLEN * DD;
    for (int idx = t; idx < 88 * 64; idx += 256) {
        int r = idx >> 6, c = idx & 63;
        int ll = l0 - 12 + r;
        ll = max(0, min(LLEN - 1, ll));
        s[r][c] = base[(long long)ll * DD + c0 + c];
    }
    __syncthreads();
    int c = t & 63, lg = t >> 6;
    int lbase = lg * 16;
    float sum = 0.f;
    #pragma unroll
    for (int r = 0; r < MAW; r++) sum += s[lbase + r][c];
    float* ob = out + (long long)b * LLEN * DD;
    ob[(long long)(l0 + lbase) * DD + c0 + c] = s[lbase + 12][c] - sum * (1.f / MAW);
    #pragma unroll
    for (int i = 1; i < 16; i++) {
        sum += s[lbase + i + 24][c] - s[lbase + i - 1][c];
        ob[(long long)(l0 + lbase + i) * DD + c0 + c] = s[lbase + i + 12][c] - sum * (1.f / MAW);
    }
}

__global__ void pool_copy_kernel(const float* __restrict__ enc, float* __restrict__ fin, int off)
{
    int b = blockIdx.x, d = threadIdx.x;
    fin[b * (NLAY * DD + HSZ) + off + d] = enc[((long long)b * LLEN + (LLEN - 1)) * DD + d];
}

__global__ __launch_bounds__(256) void rp2_kernel(
    const float* __restrict__ o2, const float* __restrict__ w,
    const float* __restrict__ bias, float* __restrict__ out)
{
    int b = blockIdx.x, t = threadIdx.x;
    __shared__ float red[256];
    red[t] = o2[b * 256 + t] * w[t];
    __syncthreads();
    for (int s = 128; s > 0; s >>= 1) { if (t < s) red[t] += red[t + s]; __syncthreads(); }
    if (t == 0) out[b] = red[0] + bias[0];
}

// =====================================================================
// launch
// =====================================================================
extern "C" void kernel_launch(void* const* d_in, const int* in_sizes, int n_in,
                              void* d_out, int out_size)
{
    (void)in_sizes; (void)n_in; (void)out_size;
    const float* x_enc     = (const float*)d_in[0];
    const float* conv1_w   = (const float*)d_in[1];
    const float* conv1_b   = (const float*)d_in[2];
    const float* conv2_w   = (const float*)d_in[3];
    const float* conv2_b   = (const float*)d_in[4];
    const float* cnn_ln_g  = (const float*)d_in[5];
    const float* cnn_ln_b  = (const float*)d_in[6];
    const float* proj_w    = (const float*)d_in[7];
    const float* proj_b    = (const float*)d_in[8];
    const float* proj_ln_g = (const float*)d_in[9];
    const float* proj_ln_b = (const float*)d_in[10];
    const float* Wq        = (const float*)d_in[11];
    const float* bq        = (const float*)d_in[12];
    const float* Wk        = (const float*)d_in[13];
    const float* bk        = (const float*)d_in[14];
    const float* Wv        = (const float*)d_in[15];
    const float* bv        = (const float*)d_in[16];
    const float* Wo        = (const float*)d_in[17];
    const float* bo        = (const float*)d_in[18];
    const float* Wff1      = (const float*)d_in[19];
    const float* Wff2      = (const float*)d_in[20];
    const float* rp1_w     = (const float*)d_in[21];
    const float* rp1_b     = (const float*)d_in[22];
    const float* rp_ln_g   = (const float*)d_in[23];
    const float* rp_ln_b   = (const float*)d_in[24];
    const float* rp2_w     = (const float*)d_in[25];
    const float* rp2_b     = (const float*)d_in[26];
    float* out = (float*)d_out;

    float *p_h1, *p_enc, *p_q, *p_k, *p_v, *p_ac, *p_xs, *p_xd, *p_big, *p_rp;
    float *p_emb, *p_final, *p_o1, *p_o2, *p_w, *p_w2t;
    int* p_del;
    cudaGetSymbolAddress((void**)&p_h1,  g_h1);
    cudaGetSymbolAddress((void**)&p_enc, g_enc);
    cudaGetSymbolAddress((void**)&p_q,   g_q);
    cudaGetSymbolAddress((void**)&p_k,   g_k);
    cudaGetSymbolAddress((void**)&p_v,   g_v);
    cudaGetSymbolAddress((void**)&p_ac,  g_ac);
    cudaGetSymbolAddress((void**)&p_xs,  g_xs);
    cudaGetSymbolAddress((void**)&p_xd,  g_xd);
    cudaGetSymbolAddress((void**)&p_big, g_big);
    cudaGetSymbolAddress((void**)&p_rp,  g_rp);
    cudaGetSymbolAddress((void**)&p_del, g_del);
    cudaGetSymbolAddress((void**)&p_w,   g_w);
    cudaGetSymbolAddress((void**)&p_emb, g_emb);
    cudaGetSymbolAddress((void**)&p_final, g_final);
    cudaGetSymbolAddress((void**)&p_o1,  g_o1);
    cudaGetSymbolAddress((void**)&p_o2,  g_o2);
    cudaGetSymbolAddress((void**)&p_w2t, g_w2t);

    const int MBL = BB * LLEN;  // 65536
    const long long SLD = (long long)LLEN * DD;

    // CNN frontend
    conv1_kernel<<<dim3(LLEN, BB), 256>>>(x_enc, conv1_w, conv1_b, p_h1);
    w2t_kernel<<<768, 256>>>(conv2_w, p_w2t);
    tgemm128<1, false, EPI_BIAS | EPI_RELU><<<dim3(2, 8, BB), 256>>>(
        p_h1, p_w2t, conv2_b, nullptr, p_xs, LLEN, DD, 768, SLD, 0, SLD);
    ln256_kernel<<<MBL / 8, 256>>>(p_xs, cnn_ln_g, cnn_ln_b, p_enc, 256, 0);

    for (int i = 0; i < NLAY; i++) {
        const float* Wq_i  = Wq + (long long)i * DD * DD;
        const float* Wk_i  = Wk + (long long)i * DD * DD;
        const float* Wv_i  = Wv + (long long)i * DD * DD;
        const float* Wo_i  = Wo + (long long)i * DD * DD;
        const float* Wf1_i = Wff1 + (long long)i * DFF * DD;
        const float* Wf2_i = Wff2 + (long long)i * DD * DFF;
        const float* bq_i = bq + i * DD;
        const float* bk_i = bk + i * DD;
        const float* bv_i = bv + i * DD;
        const float* bo_i = bo + i * DD;

        // QKV projections (tf32 TC)
        tgemm128<0, false, EPI_BIAS><<<dim3(2, 512, 1), 256>>>(p_enc, Wq_i, bq_i, nullptr, p_q, MBL, DD, DD, 0, 0, 0);
        tgemm128<0, false, EPI_BIAS><<<dim3(2, 512, 1), 256>>>(p_enc, Wk_i, bk_i, nullptr, p_k, MBL, DD, DD, 0, 0, 0);
        tgemm128<0, false, EPI_BIAS><<<dim3(2, 512, 1), 256>>>(p_enc, Wv_i, bv_i, nullptr, p_v, MBL, DD, DD, 0, 0, 0);

        // fused Gram + wrapped-diagonal reduction -> rp[b][tau]
        cudaMemsetAsync(p_rp, 0, (size_t)BB * LLEN * sizeof(float));
        tgemm128<0, true, EPI_GRAM><<<dim3(8, 8, BB), 256>>>(p_q, p_k, nullptr, nullptr, p_rp,
                                                             LLEN, LLEN, DD, SLD, SLD, LLEN);
        topk_kernel<<<BB, 256>>>(p_rp, p_del, p_w);
        agg_kernel<<<dim3(LLEN, BB), 256>>>(p_v, p_del, p_w, p_ac);

        // x = enc + (ac @ Wo + bo)
        tgemm128<0, false, EPI_BIAS | EPI_RES><<<dim3(2, 512, 1), 256>>>(p_ac, Wo_i, bo_i, p_enc, p_xs, MBL, DD, DD, 0, 0, 0);
        decomp_kernel<<<dim3(16, 4, BB), 256>>>(p_xs, p_xd);

        // FFN (tf32 TC)
        tgemm128<0, true, EPI_GELU><<<dim3(8, 512, 1), 256>>>(p_xd, Wf1_i, nullptr, nullptr, p_big, MBL, DFF, DD, 0, 0, 0);
        tgemm128<0, true, EPI_RES><<<dim3(2, 512, 1), 256>>>(p_big, Wf2_i, nullptr, p_xd, p_xs, MBL, DD, DFF, 0, 0, 0);
        decomp_kernel<<<dim3(16, 4, BB), 256>>>(p_xs, p_enc);

        pool_copy_kernel<<<BB, 256>>>(p_enc, p_final, i * DD);
    }

    // input embed head
    sgemm64<EPI_BIAS | EPI_RELU><<<dim3(4, 1), 256>>>(x_enc, proj_w, proj_b, p_emb, BB, HSZ, LLEN * CIN);
    ln256_kernel<<<BB / 8, 256>>>(p_emb, proj_ln_g, proj_ln_b, p_final, NLAY * DD + HSZ, NLAY * DD);

    // regression head
    sgemm64<EPI_BIAS | EPI_RELU><<<dim3(4, 1), 256>>>(p_final, rp1_w, rp1_b, p_o1, BB, HSZ, NLAY * DD + HSZ);
    ln256_kernel<<<BB / 8, 256>>>(p_o1, rp_ln_g, rp_ln_b, p_o2, 256, 0);
    rp2_kernel<<<BB, 256>>>(p_o2, rp2_w, rp2_b, out);
}

// round 8
// speedup vs baseline: 1.0027x; 1.0027x over previous
#include <cuda_runtime.h>
#include <cuda_bf16.h>
#include <math.h>

// ---------------- static problem config ----------------
#define BB   64
#define LLEN 1024
#define CIN  16
#define DD   256
#define HH   8
#define DFF  1024
#define HSZ  256
#define NLAY 2
#define TOPK 20
#define MAW  25   // moving average window

// ---------------- device scratch (no allocs allowed) ----------------
__device__ __align__(16) float g_h1 [BB*LLEN*DD];            // conv1 out
__device__ __align__(16) float g_enc[BB*LLEN*DD];            // encoder state
__device__ __align__(16) float g_q  [BB*LLEN*DD];
__device__ __align__(16) float g_k  [BB*LLEN*DD];
__device__ __align__(16) float g_v  [BB*LLEN*DD];
__device__ __align__(16) float g_ac [BB*LLEN*DD];            // autocorr agg out
__device__ __align__(16) float g_xs [BB*LLEN*DD];            // x (pre-decomp) / conv2 out
__device__ __align__(16) float g_xd [BB*LLEN*DD];            // x after decomp
__device__ __align__(16) float g_big[BB*LLEN*DFF];           // FFN hidden
__device__ __align__(16) float g_rp [BB*LLEN];               // correlation sums per tau
__device__ int   g_del[BB*TOPK];
__device__ float g_w  [BB*TOPK];
__device__ __align__(16) float g_emb[BB*HSZ];
__device__ __align__(16) float g_final[BB*(NLAY*DD+HSZ)];    // [64][768]
__device__ __align__(16) float g_o1[BB*HSZ];
__device__ __align__(16) float g_o2[BB*HSZ];
__device__ __align__(16) float g_w2t[768*256];               // conv2 weights as [K=768][N=256]

// ---------------- epilogue flags ----------------
#define EPI_BIAS 1
#define EPI_RELU 2
#define EPI_GELU 4
#define EPI_RES  8
#define EPI_GRAM 16   // no C tile write; reduce wrapped diagonals into C (=rp+b*1024)

__device__ __forceinline__ unsigned f2tf(float f) {
    unsigned u;
    asm("cvt.rna.tf32.f32 %0, %1;" : "=r"(u) : "f"(f));
    return u;
}

__device__ __forceinline__ void mma_tf32(float* c, const unsigned* a, const unsigned* b) {
    asm volatile(
        "mma.sync.aligned.m16n8k8.row.col.f32.tf32.tf32.f32 "
        "{%0,%1,%2,%3}, {%4,%5,%6,%7}, {%8,%9}, {%0,%1,%2,%3};\n"
        : "+f"(c[0]), "+f"(c[1]), "+f"(c[2]), "+f"(c[3])
        : "r"(a[0]), "r"(a[1]), "r"(a[2]), "r"(a[3]), "r"(b[0]), "r"(b[1]));
}

// =====================================================================
// tf32 tensor-core GEMM, 128x128x16 tile, 256 threads (8 warps),
// warp tile 64x32 (warps arranged 2 x 4), mma m16n8k8.
// (R4 mainloop: no register prefetch -- keeps regs <=128 for 2 CTA/SM.)
// AMODE: 0 = normal A [M,K]; 1 = conv2 shifted-A (A is h1[L,256], K=768,
//        k-chunk j in {0,1,2} reads row l+j-1 with zero padding).
// TB: false -> B[K,N] row-major; true -> B[N,K] row-major.
// Batched via gridDim.z with element strides sA,sB,sC.
// EPI_GRAM: instead of writing C[M,N], reduce tile into wrapped-diagonal
//           sums: C[(m-n)&1023] += acc  (C is rp + b*1024, pre-zeroed).
// =====================================================================
template<int AMODE, bool TB, int EPI>
__global__ __launch_bounds__(256) void tgemm128(
    const float* __restrict__ A, const float* __restrict__ B,
    const float* __restrict__ bias, const float* __restrict__ res,
    float* __restrict__ C, int M, int N, int K,
    long long sA, long long sB, long long sC)
{
    __shared__ unsigned As[16][136];   // stride 136: conflict-free fragment reads
    __shared__ unsigned Bs[16][136];
    __shared__ float sdiag[256];
    long long bz = blockIdx.z;
    A += bz * sA;  B += bz * sB;  C += bz * sC;
    if (EPI & EPI_RES) res += bz * sC;

    int m0 = blockIdx.y * 128, n0 = blockIdx.x * 128;
    int t = threadIdx.x;
    int wid = t >> 5, lane = t & 31;
    int g = lane >> 2, t4 = lane & 3;
    int wm = (wid & 1) * 64;
    int wn = (wid >> 1) * 32;

    float acc[4][4][4];
    #pragma unroll
    for (int mi = 0; mi < 4; mi++)
        #pragma unroll
        for (int ni = 0; ni < 4; ni++)
            #pragma unroll
            for (int r = 0; r < 4; r++) acc[mi][ni][r] = 0.f;

    const int am = t >> 1, ak = (t & 1) * 8;
    int bn, bk;
    if (TB) { bn = t >> 1;  bk = (t & 1) * 8; }
    else    { bk = t >> 4;  bn = (t & 15) * 8; }

    for (int k0 = 0; k0 < K; k0 += 16) {
        // ---- load A tile ----
        float av[8];
        if (AMODE == 0) {
            const float* ap = A + (long long)(m0 + am) * K + k0 + ak;
            float4 v0 = *(const float4*)ap;
            float4 v1 = *(const float4*)(ap + 4);
            av[0] = v0.x; av[1] = v0.y; av[2] = v0.z; av[3] = v0.w;
            av[4] = v1.x; av[5] = v1.y; av[6] = v1.z; av[7] = v1.w;
        } else {
            int kk = k0 + ak;
            int sft = kk >> 8;
            int cc  = kk & 255;
            int ll  = m0 + am + sft - 1;
            if (ll >= 0 && ll < LLEN) {
                const float* ap = A + (long long)ll * 256 + cc;
                float4 v0 = *(const float4*)ap;
                float4 v1 = *(const float4*)(ap + 4);
                av[0] = v0.x; av[1] = v0.y; av[2] = v0.z; av[3] = v0.w;
                av[4] = v1.x; av[5] = v1.y; av[6] = v1.z; av[7] = v1.w;
            } else {
                #pragma unroll
                for (int j = 0; j < 8; j++) av[j] = 0.f;
            }
        }
        #pragma unroll
        for (int j = 0; j < 8; j++) As[ak + j][am] = f2tf(av[j]);

        // ---- load B tile ----
        if (TB) {
            const float* bp = B + (long long)(n0 + bn) * K + k0 + bk;
            float4 v0 = *(const float4*)bp;
            float4 v1 = *(const float4*)(bp + 4);
            Bs[bk + 0][bn] = f2tf(v0.x); Bs[bk + 1][bn] = f2tf(v0.y);
            Bs[bk + 2][bn] = f2tf(v0.z); Bs[bk + 3][bn] = f2tf(v0.w);
            Bs[bk + 4][bn] = f2tf(v1.x); Bs[bk + 5][bn] = f2tf(v1.y);
            Bs[bk + 6][bn] = f2tf(v1.z); Bs[bk + 7][bn] = f2tf(v1.w);
        } else {
            const float* bp = B + (long long)(k0 + bk) * N + n0 + bn;
            float4 v0 = *(const float4*)bp;
            float4 v1 = *(const float4*)(bp + 4);
            Bs[bk][bn + 0] = f2tf(v0.x); Bs[bk][bn + 1] = f2tf(v0.y);
            Bs[bk][bn + 2] = f2tf(v0.z); Bs[bk][bn + 3] = f2tf(v0.w);
            Bs[bk][bn + 4] = f2tf(v1.x); Bs[bk][bn + 5] = f2tf(v1.y);
            Bs[bk][bn + 6] = f2tf(v1.z); Bs[bk][bn + 7] = f2tf(v1.w);
        }
        __syncthreads();

        // ---- mma phase: two k8 steps ----
        #pragma unroll
        for (int ks = 0; ks < 2; ks++) {
            unsigned afr[4][4], bfr[4][2];
            #pragma unroll
            for (int mi = 0; mi < 4; mi++) {
                int mr = wm + mi * 16 + g;
                afr[mi][0] = As[ks * 8 + t4][mr];
                afr[mi][1] = As[ks * 8 + t4][mr + 8];
                afr[mi][2] = As[ks * 8 + t4 + 4][mr];
                afr[mi][3] = As[ks * 8 + t4 + 4][mr + 8];
            }
            #pragma unroll
            for (int ni = 0; ni < 4; ni++) {
                int nc = wn + ni * 8 + g;
                bfr[ni][0] = Bs[ks * 8 + t4][nc];
                bfr[ni][1] = Bs[ks * 8 + t4 + 4][nc];
            }
            #pragma unroll
            for (int mi = 0; mi < 4; mi++)
                #pragma unroll
                for (int ni = 0; ni < 4; ni++)
                    mma_tf32(acc[mi][ni], afr[mi], bfr[ni]);
        }
        __syncthreads();
    }

    if (EPI & EPI_GRAM) {
        // wrapped-diagonal reduction of this 128x128 tile into tau bins.
        sdiag[t] = 0.f;
        __syncthreads();
        #pragma unroll
        for (int mi = 0; mi < 4; mi++) {
            #pragma unroll
            for (int ni = 0; ni < 4; ni++) {
                int li0 = wm + mi * 16 + g;
                int lj0 = wn + ni * 8 + t4 * 2;
                #pragma unroll
                for (int half = 0; half < 2; half++) {
                    int li = li0 + half * 8;
                    atomicAdd(&sdiag[li - lj0 + 127],     acc[mi][ni][half * 2 + 0]);
                    atomicAdd(&sdiag[li - (lj0+1) + 127], acc[mi][ni][half * 2 + 1]);
                }
            }
        }
        __syncthreads();
        if (t < 255) {
            int tau = (m0 - n0 - 127 + t) & (LLEN - 1);
            atomicAdd(&C[tau], sdiag[t]);
        }
        return;
    }

    #pragma unroll
    for (int mi = 0; mi < 4; mi++) {
        #pragma unroll
        for (int ni = 0; ni < 4; ni++) {
            long long row0 = m0 + wm + mi * 16 + g;
            int col0 = n0 + wn + ni * 8 + t4 * 2;
            #pragma unroll
            for (int half = 0; half < 2; half++) {
                long long gm = row0 + half * 8;
                float v0 = acc[mi][ni][half * 2 + 0];
                float v1 = acc[mi][ni][half * 2 + 1];
                if (EPI & EPI_BIAS) { v0 += bias[col0]; v1 += bias[col0 + 1]; }
                if (EPI & EPI_RELU) { v0 = fmaxf(v0, 0.f); v1 = fmaxf(v1, 0.f); }
                if (EPI & EPI_GELU) {
                    v0 = 0.5f * v0 * (1.f + erff(v0 * 0.70710678118654752f));
                    v1 = 0.5f * v1 * (1.f + erff(v1 * 0.70710678118654752f));
                }
                if (EPI & EPI_RES) {
                    v0 += res[gm * N + col0];
                    v1 += res[gm * N + col0 + 1];
                }
                *(float2*)(C + gm * N + col0) = make_float2(v0, v1);
            }
        }
    }
}

// transpose conv2 weights [D=256][C=256][3] -> [K=768 (j*256+c)][D=256]
__global__ void w2t_kernel(const float* __restrict__ w, float* __restrict__ o)
{
    int i = blockIdx.x * 256 + threadIdx.x;
    int d  = i & 255;
    int kk = i >> 8;
    int c  = kk & 255;
    int j  = kk >> 8;
    o[(long long)kk * 256 + d] = w[(long long)d * 768 + c * 3 + j];
}

// 64x64x16 fp32 tile version for small-M GEMMs (M=64). B is [K,N] only.
template<int EPI>
__global__ __launch_bounds__(256) void sgemm64(
    const float* __restrict__ A, const float* __restrict__ B,
    const float* __restrict__ bias, float* __restrict__ C,
    int M, int N, int K)
{
    __shared__ float As[16][64];
    __shared__ float Bs[16][64];
    int m0 = blockIdx.y * 64, n0 = blockIdx.x * 64;
    int t = threadIdx.x;
    int tx = t & 15, ty = t >> 4;
    float acc[4][4];
    #pragma unroll
    for (int i = 0; i < 4; i++)
        #pragma unroll
        for (int j = 0; j < 4; j++) acc[i][j] = 0.f;

    const int am = t >> 2, ak = (t & 3) * 4;
    const int bk = t >> 4, bn = (t & 15) * 4;

    for (int k0 = 0; k0 < K; k0 += 16) {
        float4 av = *(const float4*)(A + (long long)(m0 + am) * K + k0 + ak);
        As[ak + 0][am] = av.x; As[ak + 1][am] = av.y;
        As[ak + 2][am] = av.z; As[ak + 3][am] = av.w;
        *(float4*)&Bs[bk][bn] = *(const float4*)(B + (long long)(k0 + bk) * N + n0 + bn);
        __syncthreads();
        #pragma unroll
        for (int kk = 0; kk < 16; kk++) {
            float4 a4 = *(const float4*)&As[kk][ty * 4];
            float4 b4 = *(const float4*)&Bs[kk][tx * 4];
            float a[4] = {a4.x, a4.y, a4.z, a4.w};
            float b[4] = {b4.x, b4.y, b4.z, b4.w};
            #pragma unroll
            for (int i = 0; i < 4; i++)
                #pragma unroll
                for (int j = 0; j < 4; j++)
                    acc[i][j] += a[i] * b[j];
        }
        __syncthreads();
    }
    #pragma unroll
    for (int i = 0; i < 4; i++) {
        long long gm = m0 + ty * 4 + i;
        float vr[4];
        #pragma unroll
        for (int j = 0; j < 4; j++) {
            int gn = n0 + tx * 4 + j;
            float v = acc[i][j];
            if (EPI & EPI_BIAS) v += bias[gn];
            if (EPI & EPI_RELU) v = fmaxf(v, 0.f);
            vr[j] = v;
        }
        *(float4*)(C + gm * N + n0 + tx * 4) = make_float4(vr[0], vr[1], vr[2], vr[3]);
    }
}

// =====================================================================
// conv1: [B,L,16] -> relu(conv1d k=3 pad=1) -> [B,L,256]
// =====================================================================
__global__ __launch_bounds__(256) void conv1_kernel(
    const float* __restrict__ x, const float* __restrict__ w,
    const float* __restrict__ bias, float* __restrict__ out)
{
    int l = blockIdx.x, b = blockIdx.y, d = threadIdx.x;
    __shared__ float sx[3][16];
    if (d < 48) {
        int j = d / 16, c = d % 16;
        int ll = l + j - 1;
        sx[j][c] = (ll >= 0 && ll < LLEN) ? x[((long long)b * LLEN + ll) * CIN + c] : 0.f;
    }
    __syncthreads();
    float acc = bias[d];
    const float* wd = w + d * 48;
    #pragma unroll
    for (int c = 0; c < 16; c++)
        #pragma unroll
        for (int j = 0; j < 3; j++)
            acc += sx[j][c] * wd[c * 3 + j];
    out[((long long)b * LLEN + l) * DD + d] = fmaxf(acc, 0.f);
}

// =====================================================================
// LayerNorm over last dim = 256. 8 rows/block, 32 lanes/row, shuffle.
// =====================================================================
__global__ __launch_bounds__(256) void ln256_kernel(
    const float* __restrict__ in, const float* __restrict__ g,
    const float* __restrict__ bt, float* __restrict__ out,
    long long ostride, long long ooff)
{
    int t = threadIdx.x;
    int lane = t & 31, wr = t >> 5;
    long long r = (long long)blockIdx.x * 8 + wr;
    const float* ip = in + r * 256 + lane * 8;
    float4 v0 = *(const float4*)ip;
    float4 v1 = *(const float4*)(ip + 4);
    float x[8] = {v0.x, v0.y, v0.z, v0.w, v1.x, v1.y, v1.z, v1.w};
    float s = 0.f;
    #pragma unroll
    for (int j = 0; j < 8; j++) s += x[j];
    #pragma unroll
    for (int o = 16; o; o >>= 1) s += __shfl_xor_sync(0xFFFFFFFFu, s, o);
    float mean = s * (1.f / 256.f);
    float vs = 0.f;
    #pragma unroll
    for (int j = 0; j < 8; j++) { x[j] -= mean; vs += x[j] * x[j]; }
    #pragma unroll
    for (int o = 16; o; o >>= 1) vs += __shfl_xor_sync(0xFFFFFFFFu, vs, o);
    float inv = rsqrtf(vs * (1.f / 256.f) + 1e-5f);
    float4 g0 = *(const float4*)(g + lane * 8);
    float4 g1 = *(const float4*)(g + lane * 8 + 4);
    float4 b0 = *(const float4*)(bt + lane * 8);
    float4 b1 = *(const float4*)(bt + lane * 8 + 4);
    float gg[8] = {g0.x, g0.y, g0.z, g0.w, g1.x, g1.y, g1.z, g1.w};
    float bb[8] = {b0.x, b0.y, b0.z, b0.w, b1.x, b1.y, b1.z, b1.w};
    float o8[8];
    #pragma unroll
    for (int j = 0; j < 8; j++) o8[j] = x[j] * inv * gg[j] + bb[j];
    float* op = out + r * ostride + ooff + lane * 8;
    *(float4*)op       = make_float4(o8[0], o8[1], o8[2], o8[3]);
    *(float4*)(op + 4) = make_float4(o8[4], o8[5], o8[6], o8[7]);
}

// =====================================================================
// top-k(20) + softmax (ties -> lowest index, matches lax.top_k)
// reads rp[b][tau] (raw sums; mean = sum/256)
// =====================================================================
__global__ __launch_bounds__(256) void topk_kernel(
    const float* __restrict__ rp, int* __restrict__ del, float* __restrict__ wts)
{
    int b = blockIdx.x, t = threadIdx.x;
    __shared__ float sv[LLEN];
    __shared__ float rv[256];
    __shared__ int   ri[256];
    __shared__ float selv[TOPK];
    __shared__ int   seli[TOPK];
    for (int i = t; i < LLEN; i += 256)
        sv[i] = rp[(long long)b * LLEN + i] * (1.f / 256.f);
    __syncthreads();
    for (int iter = 0; iter < TOPK; iter++) {
        float bv = -INFINITY; int bi = 1 << 30;
        for (int i = t; i < LLEN; i += 256) {
            float v = sv[i];
            if (v > bv || (v == bv && i < bi)) { bv = v; bi = i; }
        }
        rv[t] = bv; ri[t] = bi; __syncthreads();
        for (int s = 128; s > 0; s >>= 1) {
            if (t < s) {
                if (rv[t + s] > rv[t] || (rv[t + s] == rv[t] && ri[t + s] < ri[t])) {
                    rv[t] = rv[t + s]; ri[t] = ri[t + s];
                }
            }
            __syncthreads();
        }
        if (t == 0) { selv[iter] = rv[0]; seli[iter] = ri[0]; sv[ri[0]] = -INFINITY; }
        __syncthreads();
    }
    if (t == 0) {
        float m = selv[0];
        float e[TOPK], ssum = 0.f;
        for (int k2 = 0; k2 < TOPK; k2++) { e[k2] = expf(selv[k2] - m); ssum += e[k2]; }
        float inv = 1.f / ssum;
        for (int k2 = 0; k2 < TOPK; k2++) {
            wts[b * TOPK + k2] = e[k2] * inv;
            del[b * TOPK + k2] = seli[k2];
        }
    }
}

// =====================================================================
// delayed aggregation: out[b,l,d] = sum_k w[k] * V[b,(l+delay[k])%L,d]
// 4 rows per block, float4 over d (64 lanes per row).
// =====================================================================
__global__ __launch_bounds__(256) void agg_kernel(
    const float* __restrict__ V, const int* __restrict__ del,
    const float* __restrict__ wts, float* __restrict__ out)
{
    int t = threadIdx.x;
    int b = blockIdx.y;
    int l = blockIdx.x * 4 + (t >> 6);
    int d4 = (t & 63) * 4;
    __shared__ int   sd[TOPK];
    __shared__ float sw[TOPK];
    if (t < TOPK) { sd[t] = del[b * TOPK + t]; sw[t] = wts[b * TOPK + t]; }
    __syncthreads();
    const float* vb = V + (long long)b * LLEN * DD;
    float a0 = 0.f, a1 = 0.f, a2 = 0.f, a3 = 0.f;
    #pragma unroll
    for (int k2 = 0; k2 < TOPK; k2++) {
        float w = sw[k2];
        float4 v = *(const float4*)(vb + (long long)((l + sd[k2]) & (LLEN - 1)) * DD + d4);
        a0 += w * v.x; a1 += w * v.y; a2 += w * v.z; a3 += w * v.w;
    }
    *(float4*)(out + ((long long)b * LLEN + l) * DD + d4) = make_float4(a0, a1, a2, a3);
}

// =====================================================================
// series decomposition: out = in - movavg25(in, replicate-pad)
// =====================================================================
__global__ __launch_bounds__(256) void decomp_kernel(
    const float* __restrict__ in, float* __restrict__ out)
{
    __shared__ float s[88][65];
    int b  = blockIdx.z;
    int c0 = blockIdx.y * 64;
    int l0 = blockIdx.x * 64;
    int t  = threadIdx.x;
    const float* base = in + (long long)b * LLEN * DD;
    for (int idx = t; idx < 88 * 64; idx += 256) {
        int r = idx >> 6, c = idx & 63;
        int ll = l0 - 12 + r;
        ll = max(0, min(LLEN - 1, ll));
        s[r][c] = base[(long long)ll * DD + c0 + c];
    }
    __syncthreads();
    int c = t & 63, lg = t >> 6;
    int lbase = lg * 16;
    float sum = 0.f;
    #pragma unroll
    for (int r = 0; r < MAW; r++) sum += s[lbase + r][c];
    float* ob = out + (long long)b * LLEN * DD;
    ob[(long long)(l0 + lbase) * DD + c0 + c] = s[lbase + 12][c] - sum * (1.f / MAW);
    #pragma unroll
    for (int i = 1; i < 16; i++) {
        sum += s[lbase + i + 24][c] - s[lbase + i - 1][c];
        ob[(long long)(l0 + lbase + i) * DD + c0 + c] = s[lbase + i + 12][c] - sum * (1.f / MAW);
    }
}

__global__ void pool_copy_kernel(const float* __restrict__ enc, float* __restrict__ fin, int off)
{
    int b = blockIdx.x, d = threadIdx.x;
    fin[b * (NLAY * DD + HSZ) + off + d] = enc[((long long)b * LLEN + (LLEN - 1)) * DD + d];
}

__global__ __launch_bounds__(256) void rp2_kernel(
    const float* __restrict__ o2, const float* __restrict__ w,
    const float* __restrict__ bias, float* __restrict__ out)
{
    int b = blockIdx.x, t = threadIdx.x;
    __shared__ float red[256];
    red[t] = o2[b * 256 + t] * w[t];
    __syncthreads();
    for (int s = 128; s > 0; s >>= 1) { if (t < s) red[t] += red[t + s]; __syncthreads(); }
    if (t == 0) out[b] = red[0] + bias[0];
}

// =====================================================================
// launch
// =====================================================================
extern "C" void kernel_launch(void* const* d_in, const int* in_sizes, int n_in,
                              void* d_out, int out_size)
{
    (void)in_sizes; (void)n_in; (void)out_size;
    const float* x_enc     = (const float*)d_in[0];
    const float* conv1_w   = (const float*)d_in[1];
    const float* conv1_b   = (const float*)d_in[2];
    const float* conv2_w   = (const float*)d_in[3];
    const float* conv2_b   = (const float*)d_in[4];
    const float* cnn_ln_g  = (const float*)d_in[5];
    const float* cnn_ln_b  = (const float*)d_in[6];
    const float* proj_w    = (const float*)d_in[7];
    const float* proj_b    = (const float*)d_in[8];
    const float* proj_ln_g = (const float*)d_in[9];
    const float* proj_ln_b = (const float*)d_in[10];
    const float* Wq        = (const float*)d_in[11];
    const float* bq        = (const float*)d_in[12];
    const float* Wk        = (const float*)d_in[13];
    const float* bk        = (const float*)d_in[14];
    const float* Wv        = (const float*)d_in[15];
    const float* bv        = (const float*)d_in[16];
    const float* Wo        = (const float*)d_in[17];
    const float* bo        = (const float*)d_in[18];
    const float* Wff1      = (const float*)d_in[19];
    const float* Wff2      = (const float*)d_in[20];
    const float* rp1_w     = (const float*)d_in[21];
    const float* rp1_b     = (const float*)d_in[22];
    const float* rp_ln_g   = (const float*)d_in[23];
    const float* rp_ln_b   = (const float*)d_in[24];
    const float* rp2_w     = (const float*)d_in[25];
    const float* rp2_b     = (const float*)d_in[26];
    float* out = (float*)d_out;

    float *p_h1, *p_enc, *p_q, *p_k, *p_v, *p_ac, *p_xs, *p_xd, *p_big, *p_rp;
    float *p_emb, *p_final, *p_o1, *p_o2, *p_w, *p_w2t;
    int* p_del;
    cudaGetSymbolAddress((void**)&p_h1,  g_h1);
    cudaGetSymbolAddress((void**)&p_enc, g_enc);
    cudaGetSymbolAddress((void**)&p_q,   g_q);
    cudaGetSymbolAddress((void**)&p_k,   g_k);
    cudaGetSymbolAddress((void**)&p_v,   g_v);
    cudaGetSymbolAddress((void**)&p_ac,  g_ac);
    cudaGetSymbolAddress((void**)&p_xs,  g_xs);
    cudaGetSymbolAddress((void**)&p_xd,  g_xd);
    cudaGetSymbolAddress((void**)&p_big, g_big);
    cudaGetSymbolAddress((void**)&p_rp,  g_rp);
    cudaGetSymbolAddress((void**)&p_del, g_del);
    cudaGetSymbolAddress((void**)&p_w,   g_w);
    cudaGetSymbolAddress((void**)&p_emb, g_emb);
    cudaGetSymbolAddress((void**)&p_final, g_final);
    cudaGetSymbolAddress((void**)&p_o1,  g_o1);
    cudaGetSymbolAddress((void**)&p_o2,  g_o2);
    cudaGetSymbolAddress((void**)&p_w2t, g_w2t);

    const int MBL = BB * LLEN;  // 65536
    const long long SLD = (long long)LLEN * DD;

    // CNN frontend
    conv1_kernel<<<dim3(LLEN, BB), 256>>>(x_enc, conv1_w, conv1_b, p_h1);
    w2t_kernel<<<768, 256>>>(conv2_w, p_w2t);
    tgemm128<1, false, EPI_BIAS | EPI_RELU><<<dim3(2, 8, BB), 256>>>(
        p_h1, p_w2t, conv2_b, nullptr, p_xs, LLEN, DD, 768, SLD, 0, SLD);
    ln256_kernel<<<MBL / 8, 256>>>(p_xs, cnn_ln_g, cnn_ln_b, p_enc, 256, 0);

    for (int i = 0; i < NLAY; i++) {
        const float* Wq_i  = Wq + (long long)i * DD * DD;
        const float* Wk_i  = Wk + (long long)i * DD * DD;
        const float* Wv_i  = Wv + (long long)i * DD * DD;
        const float* Wo_i  = Wo + (long long)i * DD * DD;
        const float* Wf1_i = Wff1 + (long long)i * DFF * DD;
        const float* Wf2_i = Wff2 + (long long)i * DD * DFF;
        const float* bq_i = bq + i * DD;
        const float* bk_i = bk + i * DD;
        const float* bv_i = bv + i * DD;
        const float* bo_i = bo + i * DD;

        // QKV projections (tf32 TC)
        tgemm128<0, false, EPI_BIAS><<<dim3(2, 512, 1), 256>>>(p_enc, Wq_i, bq_i, nullptr, p_q, MBL, DD, DD, 0, 0, 0);
        tgemm128<0, false, EPI_BIAS><<<dim3(2, 512, 1), 256>>>(p_enc, Wk_i, bk_i, nullptr, p_k, MBL, DD, DD, 0, 0, 0);
        tgemm128<0, false, EPI_BIAS><<<dim3(2, 512, 1), 256>>>(p_enc, Wv_i, bv_i, nullptr, p_v, MBL, DD, DD, 0, 0, 0);

        // fused Gram + wrapped-diagonal reduction -> rp[b][tau]
        cudaMemsetAsync(p_rp, 0, (size_t)BB * LLEN * sizeof(float));
        tgemm128<0, true, EPI_GRAM><<<dim3(8, 8, BB), 256>>>(p_q, p_k, nullptr, nullptr, p_rp,
                                                             LLEN, LLEN, DD, SLD, SLD, LLEN);
        topk_kernel<<<BB, 256>>>(p_rp, p_del, p_w);
        agg_kernel<<<dim3(LLEN / 4, BB), 256>>>(p_v, p_del, p_w, p_ac);

        // x = enc + (ac @ Wo + bo)
        tgemm128<0, false, EPI_BIAS | EPI_RES><<<dim3(2, 512, 1), 256>>>(p_ac, Wo_i, bo_i, p_enc, p_xs, MBL, DD, DD, 0, 0, 0);
        decomp_kernel<<<dim3(16, 4, BB), 256>>>(p_xs, p_xd);

        // FFN (tf32 TC)
        tgemm128<0, true, EPI_GELU><<<dim3(8, 512, 1), 256>>>(p_xd, Wf1_i, nullptr, nullptr, p_big, MBL, DFF, DD, 0, 0, 0);
        tgemm128<0, true, EPI_RES><<<dim3(2, 512, 1), 256>>>(p_big, Wf2_i, nullptr, p_xd, p_xs, MBL, DD, DFF, 0, 0, 0);
        decomp_kernel<<<dim3(16, 4, BB), 256>>>(p_xs, p_enc);

        pool_copy_kernel<<<BB, 256>>>(p_enc, p_final, i * DD);
    }

    // input embed head
    sgemm64<EPI_BIAS | EPI_RELU><<<dim3(4, 1), 256>>>(x_enc, proj_w, proj_b, p_emb, BB, HSZ, LLEN * CIN);
    ln256_kernel<<<BB / 8, 256>>>(p_emb, proj_ln_g, proj_ln_b, p_final, NLAY * DD + HSZ, NLAY * DD);

    // regression head
    sgemm64<EPI_BIAS | EPI_RELU><<<dim3(4, 1), 256>>>(p_final, rp1_w, rp1_b, p_o1, BB, HSZ, NLAY * DD + HSZ);
    ln256_kernel<<<BB / 8, 256>>>(p_o1, rp_ln_g, rp_ln_b, p_o2, 256, 0);
    rp2_kernel<<<BB, 256>>>(p_o2, rp2_w, rp2_b, out);
}

// round 9
// speedup vs baseline: 1.0763x; 1.0734x over previous
#include <cuda_runtime.h>
#include <cuda_bf16.h>
#include <math.h>

// ---------------- static problem config ----------------
#define BB   64
#define LLEN 1024
#define CIN  16
#define DD   256
#define HH   8
#define DFF  1024
#define HSZ  256
#define NLAY 2
#define TOPK 20
#define MAW  25   // moving average window

// ---------------- device scratch (no allocs allowed) ----------------
__device__ __align__(16) float g_h1 [BB*LLEN*DD];            // conv1 out
__device__ __align__(16) float g_enc[BB*LLEN*DD];            // encoder state
__device__ __align__(16) float g_q  [BB*LLEN*DD];
__device__ __align__(16) float g_k  [BB*LLEN*DD];
__device__ __align__(16) float g_v  [BB*LLEN*DD];
__device__ __align__(16) float g_ac [BB*LLEN*DD];            // autocorr agg out
__device__ __align__(16) float g_xs [BB*LLEN*DD];            // x (pre-decomp) / conv2 out
__device__ __align__(16) float g_xd [BB*LLEN*DD];            // x after decomp
__device__ __align__(16) float g_big[BB*LLEN*DFF];           // FFN hidden
__device__ __align__(16) float g_rp [BB*LLEN];               // correlation sums per tau
__device__ int   g_del[BB*TOPK];
__device__ float g_w  [BB*TOPK];
__device__ __align__(16) float g_emb[BB*HSZ];
__device__ __align__(16) float g_final[BB*(NLAY*DD+HSZ)];    // [64][768]
__device__ __align__(16) float g_o1[BB*HSZ];
__device__ __align__(16) float g_o2[BB*HSZ];
__device__ __align__(16) float g_w2t[768*256];               // conv2 weights as [K=768][N=256]

// ---------------- epilogue flags ----------------
#define EPI_BIAS 1
#define EPI_RELU 2
#define EPI_GELU 4
#define EPI_RES  8
#define EPI_GRAM 16   // no C tile write; reduce wrapped diagonals into C (=rp+b*1024)

__device__ __forceinline__ unsigned f2tf(float f) {
    unsigned u;
    asm("cvt.rna.tf32.f32 %0, %1;" : "=r"(u) : "f"(f));
    return u;
}

__device__ __forceinline__ void mma_tf32(float* c, const unsigned* a, const unsigned* b) {
    asm volatile(
        "mma.sync.aligned.m16n8k8.row.col.f32.tf32.tf32.f32 "
        "{%0,%1,%2,%3}, {%4,%5,%6,%7}, {%8,%9}, {%0,%1,%2,%3};\n"
        : "+f"(c[0]), "+f"(c[1]), "+f"(c[2]), "+f"(c[3])
        : "r"(a[0]), "r"(a[1]), "r"(a[2]), "r"(a[3]), "r"(b[0]), "r"(b[1]));
}

// 16B cp.async with zero-fill predicate (src_size = 0 -> all zeros)
__device__ __forceinline__ void cp16(unsigned smem_addr, const void* gptr, bool pred) {
    int sz = pred ? 16 : 0;
    asm volatile("cp.async.cg.shared.global [%0], [%1], 16, %2;\n"
                 :: "r"(smem_addr), "l"(gptr), "r"(sz));
}
__device__ __forceinline__ void cp_commit() {
    asm volatile("cp.async.commit_group;\n");
}
__device__ __forceinline__ void cp_wait0() {
    asm volatile("cp.async.wait_group 0;\n");
}

// =====================================================================
// tf32 tensor-core GEMM, 128x128x16 tile, 256 threads (8 warps),
// warp tile 64x32 (warps 2 x 4), mma m16n8k8.
// 2-stage cp.async double-buffered pipeline: copy of tile i+1 overlaps
// the mma phase of tile i. Tiles live in smem as RAW fp32; tf32
// rounding (cvt.rna) is applied at fragment load -- identical math to
// converting at smem-store time.
//
// smem layouts (conflict-free fragment reads + 16B cp.async chunks):
//   A (and TB-true B): [row][k], row stride 20 floats
//   TB-false B:        [k][n],   k stride 136 floats
//
// AMODE: 0 = normal A [M,K]; 1 = conv2 shifted-A (A is h1[L,256], K=768,
//        k-chunk j in {0,1,2} reads row l+j-1 with zero padding).
// TB: false -> B[K,N] row-major; true -> B[N,K] row-major.
// Batched via gridDim.z with element strides sA,sB,sC.
// EPI_GRAM: instead of writing C[M,N], reduce tile into wrapped-diagonal
//           sums: C[(m-n)&1023] += acc  (C is rp + b*1024, pre-zeroed).
// =====================================================================
#define ASTRIDE 20
#define ASTAGE  (128 * ASTRIDE)   // 2560 floats per stage
#define BSTAGE  2720              // max(128*20, 16*136) floats per stage

template<int AMODE, bool TB, int EPI>
__global__ __launch_bounds__(256) void tgemm128(
    const float* __restrict__ A, const float* __restrict__ B,
    const float* __restrict__ bias, const float* __restrict__ res,
    float* __restrict__ C, int M, int N, int K,
    long long sA, long long sB, long long sC)
{
    __shared__ float Asm[2 * ASTAGE];
    __shared__ float Bsm[2 * BSTAGE];
    __shared__ float sdiag[256];
    long long bz = blockIdx.z;
    A += bz * sA;  B += bz * sB;  C += bz * sC;
    if (EPI & EPI_RES) res += bz * sC;

    int m0 = blockIdx.y * 128, n0 = blockIdx.x * 128;
    int t = threadIdx.x;
    int wid = t >> 5, lane = t & 31;
    int g = lane >> 2, t4 = lane & 3;
    int wm = (wid & 1) * 64;
    int wn = (wid >> 1) * 32;

    unsigned sA_u = (unsigned)__cvta_generic_to_shared(Asm);
    unsigned sB_u = (unsigned)__cvta_generic_to_shared(Bsm);

    float acc[4][4][4];
    #pragma unroll
    for (int mi = 0; mi < 4; mi++)
        #pragma unroll
        for (int ni = 0; ni < 4; ni++)
            #pragma unroll
            for (int r = 0; r < 4; r++) acc[mi][ni][r] = 0.f;

    // per-thread copy assignment (2 x 16B chunks for A, 2 for B)
    const int arow = t >> 1, ac0 = (t & 1) * 8;
    int brow, bc0;
    if (TB) { brow = t >> 1;  bc0 = (t & 1) * 8; }   // [n][k]
    else    { brow = t >> 4;  bc0 = (t & 15) * 8; }  // [k][n]

#define ISSUE_COPY(ST, K0)                                                     \
    {                                                                          \
        unsigned as = sA_u + ((ST) * ASTAGE + arow * ASTRIDE + ac0) * 4;       \
        if (AMODE == 0) {                                                      \
            const float* gp = A + (long long)(m0 + arow) * K + (K0) + ac0;     \
            cp16(as, gp, true);  cp16(as + 16, gp + 4, true);                  \
        } else {                                                               \
            int kk = (K0) + ac0;                                               \
            int sft = kk >> 8;                                                 \
            int cc  = kk & 255;                                                \
            int ll  = m0 + arow + sft - 1;                                     \
            bool ok = (ll >= 0 && ll < LLEN);                                  \
            const float* gp = ok ? (A + (long long)ll * 256 + cc) : A;         \
            cp16(as, gp, ok);  cp16(as + 16, gp + 4, ok);                      \
        }                                                                      \
        if (TB) {                                                              \
            unsigned bs = sB_u + ((ST) * BSTAGE + brow * ASTRIDE + bc0) * 4;   \
            const float* gp = B + (long long)(n0 + brow) * K + (K0) + bc0;     \
            cp16(bs, gp, true);  cp16(bs + 16, gp + 4, true);                  \
        } else {                                                               \
            unsigned bs = sB_u + ((ST) * BSTAGE + brow * 136 + bc0) * 4;       \
            const float* gp = B + (long long)((K0) + brow) * N + n0 + bc0;     \
            cp16(bs, gp, true);  cp16(bs + 16, gp + 4, true);                  \
        }                                                                      \
    }

    const int KT = K / 16;
    ISSUE_COPY(0, 0);
    cp_commit();

    for (int it = 0; it < KT; it++) {
        cp_wait0();
        __syncthreads();
        if (it + 1 < KT) ISSUE_COPY((it + 1) & 1, (it + 1) * 16);
        cp_commit();

        const float* As = Asm + (it & 1) * ASTAGE;
        const float* Bsr = Bsm + (it & 1) * BSTAGE;

        #pragma unroll
        for (int ks = 0; ks < 2; ks++) {
            int k0f = ks * 8 + t4;
            unsigned afr[4][4], bfr[4][2];
            #pragma unroll
            for (int mi = 0; mi < 4; mi++) {
                int mr = wm + mi * 16 + g;
                afr[mi][0] = f2tf(As[mr * ASTRIDE + k0f]);
                afr[mi][1] = f2tf(As[(mr + 8) * ASTRIDE + k0f]);
                afr[mi][2] = f2tf(As[mr * ASTRIDE + k0f + 4]);
                afr[mi][3] = f2tf(As[(mr + 8) * ASTRIDE + k0f + 4]);
            }
            #pragma unroll
            for (int ni = 0; ni < 4; ni++) {
                int nc = wn + ni * 8 + g;
                if (TB) {
                    bfr[ni][0] = f2tf(Bsr[nc * ASTRIDE + k0f]);
                    bfr[ni][1] = f2tf(Bsr[nc * ASTRIDE + k0f + 4]);
                } else {
                    bfr[ni][0] = f2tf(Bsr[k0f * 136 + nc]);
                    bfr[ni][1] = f2tf(Bsr[(k0f + 4) * 136 + nc]);
                }
            }
            #pragma unroll
            for (int mi = 0; mi < 4; mi++)
                #pragma unroll
                for (int ni = 0; ni < 4; ni++)
                    mma_tf32(acc[mi][ni], afr[mi], bfr[ni]);
        }
        __syncthreads();
    }
#undef ISSUE_COPY

    if (EPI & EPI_GRAM) {
        // wrapped-diagonal reduction of this 128x128 tile into tau bins.
        sdiag[t] = 0.f;
        __syncthreads();
        #pragma unroll
        for (int mi = 0; mi < 4; mi++) {
            #pragma unroll
            for (int ni = 0; ni < 4; ni++) {
                int li0 = wm + mi * 16 + g;
                int lj0 = wn + ni * 8 + t4 * 2;
                #pragma unroll
                for (int half = 0; half < 2; half++) {
                    int li = li0 + half * 8;
                    atomicAdd(&sdiag[li - lj0 + 127],     acc[mi][ni][half * 2 + 0]);
                    atomicAdd(&sdiag[li - (lj0+1) + 127], acc[mi][ni][half * 2 + 1]);
                }
            }
        }
        __syncthreads();
        if (t < 255) {
            int tau = (m0 - n0 - 127 + t) & (LLEN - 1);
            atomicAdd(&C[tau], sdiag[t]);
        }
        return;
    }

    #pragma unroll
    for (int mi = 0; mi < 4; mi++) {
        #pragma unroll
        for (int ni = 0; ni < 4; ni++) {
            long long row0 = m0 + wm + mi * 16 + g;
            int col0 = n0 + wn + ni * 8 + t4 * 2;
            #pragma unroll
            for (int half = 0; half < 2; half++) {
                long long gm = row0 + half * 8;
                float v0 = acc[mi][ni][half * 2 + 0];
                float v1 = acc[mi][ni][half * 2 + 1];
                if (EPI & EPI_BIAS) { v0 += bias[col0]; v1 += bias[col0 + 1]; }
                if (EPI & EPI_RELU) { v0 = fmaxf(v0, 0.f); v1 = fmaxf(v1, 0.f); }
                if (EPI & EPI_GELU) {
                    v0 = 0.5f * v0 * (1.f + erff(v0 * 0.70710678118654752f));
                    v1 = 0.5f * v1 * (1.f + erff(v1 * 0.70710678118654752f));
                }
                if (EPI & EPI_RES) {
                    v0 += res[gm * N + col0];
                    v1 += res[gm * N + col0 + 1];
                }
                *(float2*)(C + gm * N + col0) = make_float2(v0, v1);
            }
        }
    }
}

// transpose conv2 weights [D=256][C=256][3] -> [K=768 (j*256+c)][D=256]
__global__ void w2t_kernel(const float* __restrict__ w, float* __restrict__ o)
{
    int i = blockIdx.x * 256 + threadIdx.x;
    int d  = i & 255;
    int kk = i >> 8;
    int c  = kk & 255;
    int j  = kk >> 8;
    o[(long long)kk * 256 + d] = w[(long long)d * 768 + c * 3 + j];
}

// 64x64x16 fp32 tile version for small-M GEMMs (M=64). B is [K,N] only.
template<int EPI>
__global__ __launch_bounds__(256) void sgemm64(
    const float* __restrict__ A, const float* __restrict__ B,
    const float* __restrict__ bias, float* __restrict__ C,
    int M, int N, int K)
{
    __shared__ float As[16][64];
    __shared__ float Bs[16][64];
    int m0 = blockIdx.y * 64, n0 = blockIdx.x * 64;
    int t = threadIdx.x;
    int tx = t & 15, ty = t >> 4;
    float acc[4][4];
    #pragma unroll
    for (int i = 0; i < 4; i++)
        #pragma unroll
        for (int j = 0; j < 4; j++) acc[i][j] = 0.f;

    const int am = t >> 2, ak = (t & 3) * 4;
    const int bk = t >> 4, bn = (t & 15) * 4;

    for (int k0 = 0; k0 < K; k0 += 16) {
        float4 av = *(const float4*)(A + (long long)(m0 + am) * K + k0 + ak);
        As[ak + 0][am] = av.x; As[ak + 1][am] = av.y;
        As[ak + 2][am] = av.z; As[ak + 3][am] = av.w;
        *(float4*)&Bs[bk][bn] = *(const float4*)(B + (long long)(k0 + bk) * N + n0 + bn);
        __syncthreads();
        #pragma unroll
        for (int kk = 0; kk < 16; kk++) {
            float4 a4 = *(const float4*)&As[kk][ty * 4];
            float4 b4 = *(const float4*)&Bs[kk][tx * 4];
            float a[4] = {a4.x, a4.y, a4.z, a4.w};
            float b[4] = {b4.x, b4.y, b4.z, b4.w};
            #pragma unroll
            for (int i = 0; i < 4; i++)
                #pragma unroll
                for (int j = 0; j < 4; j++)
                    acc[i][j] += a[i] * b[j];
        }
        __syncthreads();
    }
    #pragma unroll
    for (int i = 0; i < 4; i++) {
        long long gm = m0 + ty * 4 + i;
        float vr[4];
        #pragma unroll
        for (int j = 0; j < 4; j++) {
            int gn = n0 + tx * 4 + j;
            float v = acc[i][j];
            if (EPI & EPI_BIAS) v += bias[gn];
            if (EPI & EPI_RELU) v = fmaxf(v, 0.f);
            vr[j] = v;
        }
        *(float4*)(C + gm * N + n0 + tx * 4) = make_float4(vr[0], vr[1], vr[2], vr[3]);
    }
}

// =====================================================================
// conv1: [B,L,16] -> relu(conv1d k=3 pad=1) -> [B,L,256]
// =====================================================================
__global__ __launch_bounds__(256) void conv1_kernel(
    const float* __restrict__ x, const float* __restrict__ w,
    const float* __restrict__ bias, float* __restrict__ out)
{
    int l = blockIdx.x, b = blockIdx.y, d = threadIdx.x;
    __shared__ float sx[3][16];
    if (d < 48) {
        int j = d / 16, c = d % 16;
        int ll = l + j - 1;
        sx[j][c] = (ll >= 0 && ll < LLEN) ? x[((long long)b * LLEN + ll) * CIN + c] : 0.f;
    }
    __syncthreads();
    float acc = bias[d];
    const float* wd = w + d * 48;
    #pragma unroll
    for (int c = 0; c < 16; c++)
        #pragma unroll
        for (int j = 0; j < 3; j++)
            acc += sx[j][c] * wd[c * 3 + j];
    out[((long long)b * LLEN + l) * DD + d] = fmaxf(acc, 0.f);
}

// =====================================================================
// LayerNorm over last dim = 256. 8 rows/block, 32 lanes/row, shuffle.
// =====================================================================
__global__ __launch_bounds__(256) void ln256_kernel(
    const float* __restrict__ in, const float* __restrict__ g,
    const float* __restrict__ bt, float* __restrict__ out,
    long long ostride, long long ooff)
{
    int t = threadIdx.x;
    int lane = t & 31, wr = t >> 5;
    long long r = (long long)blockIdx.x * 8 + wr;
    const float* ip = in + r * 256 + lane * 8;
    float4 v0 = *(const float4*)ip;
    float4 v1 = *(const float4*)(ip + 4);
    float x[8] = {v0.x, v0.y, v0.z, v0.w, v1.x, v1.y, v1.z, v1.w};
    float s = 0.f;
    #pragma unroll
    for (int j = 0; j < 8; j++) s += x[j];
    #pragma unroll
    for (int o = 16; o; o >>= 1) s += __shfl_xor_sync(0xFFFFFFFFu, s, o);
    float mean = s * (1.f / 256.f);
    float vs = 0.f;
    #pragma unroll
    for (int j = 0; j < 8; j++) { x[j] -= mean; vs += x[j] * x[j]; }
    #pragma unroll
    for (int o = 16; o; o >>= 1) vs += __shfl_xor_sync(0xFFFFFFFFu, vs, o);
    float inv = rsqrtf(vs * (1.f / 256.f) + 1e-5f);
    float4 g0 = *(const float4*)(g + lane * 8);
    float4 g1 = *(const float4*)(g + lane * 8 + 4);
    float4 b0 = *(const float4*)(bt + lane * 8);
    float4 b1 = *(const float4*)(bt + lane * 8 + 4);
    float gg[8] = {g0.x, g0.y, g0.z, g0.w, g1.x, g1.y, g1.z, g1.w};
    float bb[8] = {b0.x, b0.y, b0.z, b0.w, b1.x, b1.y, b1.z, b1.w};
    float o8[8];
    #pragma unroll
    for (int j = 0; j < 8; j++) o8[j] = x[j] * inv * gg[j] + bb[j];
    float* op = out + r * ostride + ooff + lane * 8;
    *(float4*)op       = make_float4(o8[0], o8[1], o8[2], o8[3]);
    *(float4*)(op + 4) = make_float4(o8[4], o8[5], o8[6], o8[7]);
}

// =====================================================================
// top-k(20) + softmax (ties -> lowest index, matches lax.top_k)
// reads rp[b][tau] (raw sums; mean = sum/256)
// =====================================================================
__global__ __launch_bounds__(256) void topk_kernel(
    const float* __restrict__ rp, int* __restrict__ del, float* __restrict__ wts)
{
    int b = blockIdx.x, t = threadIdx.x;
    __shared__ float sv[LLEN];
    __shared__ float rv[256];
    __shared__ int   ri[256];
    __shared__ float selv[TOPK];
    __shared__ int   seli[TOPK];
    for (int i = t; i < LLEN; i += 256)
        sv[i] = rp[(long long)b * LLEN + i] * (1.f / 256.f);
    __syncthreads();
    for (int iter = 0; iter < TOPK; iter++) {
        float bv = -INFINITY; int bi = 1 << 30;
        for (int i = t; i < LLEN; i += 256) {
            float v = sv[i];
            if (v > bv || (v == bv && i < bi)) { bv = v; bi = i; }
        }
        rv[t] = bv; ri[t] = bi; __syncthreads();
        for (int s = 128; s > 0; s >>= 1) {
            if (t < s) {
                if (rv[t + s] > rv[t] || (rv[t + s] == rv[t] && ri[t + s] < ri[t])) {
                    rv[t] = rv[t + s]; ri[t] = ri[t + s];
                }
            }
            __syncthreads();
        }
        if (t == 0) { selv[iter] = rv[0]; seli[iter] = ri[0]; sv[ri[0]] = -INFINITY; }
        __syncthreads();
    }
    if (t == 0) {
        float m = selv[0];
        float e[TOPK], ssum = 0.f;
        for (int k2 = 0; k2 < TOPK; k2++) { e[k2] = expf(selv[k2] - m); ssum += e[k2]; }
        float inv = 1.f / ssum;
        for (int k2 = 0; k2 < TOPK; k2++) {
            wts[b * TOPK + k2] = e[k2] * inv;
            del[b * TOPK + k2] = seli[k2];
        }
    }
}

// =====================================================================
// delayed aggregation: out[b,l,d] = sum_k w[k] * V[b,(l+delay[k])%L,d]
// 4 rows per block, float4 over d (64 lanes per row).
// =====================================================================
__global__ __launch_bounds__(256) void agg_kernel(
    const float* __restrict__ V, const int* __restrict__ del,
    const float* __restrict__ wts, float* __restrict__ out)
{
    int t = threadIdx.x;
    int b = blockIdx.y;
    int l = blockIdx.x * 4 + (t >> 6);
    int d4 = (t & 63) * 4;
    __shared__ int   sd[TOPK];
    __shared__ float sw[TOPK];
    if (t < TOPK) { sd[t] = del[b * TOPK + t]; sw[t] = wts[b * TOPK + t]; }
    __syncthreads();
    const float* vb = V + (long long)b * LLEN * DD;
    float a0 = 0.f, a1 = 0.f, a2 = 0.f, a3 = 0.f;
    #pragma unroll
    for (int k2 = 0; k2 < TOPK; k2++) {
        float w = sw[k2];
        float4 v = *(const float4*)(vb + (long long)((l + sd[k2]) & (LLEN - 1)) * DD + d4);
        a0 += w * v.x; a1 += w * v.y; a2 += w * v.z; a3 += w * v.w;
    }
    *(float4*)(out + ((long long)b * LLEN + l) * DD + d4) = make_float4(a0, a1, a2, a3);
}

// =====================================================================
// series decomposition: out = in - movavg25(in, replicate-pad)
// =====================================================================
__global__ __launch_bounds__(256) void decomp_kernel(
    const float* __restrict__ in, float* __restrict__ out)
{
    __shared__ float s[88][65];
    int b  = blockIdx.z;
    int c0 = blockIdx.y * 64;
    int l0 = blockIdx.x * 64;
    int t  = threadIdx.x;
    const float* base = in + (long long)b * LLEN * DD;
    for (int idx = t; idx < 88 * 64; idx += 256) {
        int r = idx >> 6, c = idx & 63;
        int ll = l0 - 12 + r;
        ll = max(0, min(LLEN - 1, ll));
        s[r][c] = base[(long long)ll * DD + c0 + c];
    }
    __syncthreads();
    int c = t & 63, lg = t >> 6;
    int lbase = lg * 16;
    float sum = 0.f;
    #pragma unroll
    for (int r = 0; r < MAW; r++) sum += s[lbase + r][c];
    float* ob = out + (long long)b * LLEN * DD;
    ob[(long long)(l0 + lbase) * DD + c0 + c] = s[lbase + 12][c] - sum * (1.f / MAW);
    #pragma unroll
    for (int i = 1; i < 16; i++) {
        sum += s[lbase + i + 24][c] - s[lbase + i - 1][c];
        ob[(long long)(l0 + lbase + i) * DD + c0 + c] = s[lbase + i + 12][c] - sum * (1.f / MAW);
    }
}

__global__ void pool_copy_kernel(const float* __restrict__ enc, float* __restrict__ fin, int off)
{
    int b = blockIdx.x, d = threadIdx.x;
    fin[b * (NLAY * DD + HSZ) + off + d] = enc[((long long)b * LLEN + (LLEN - 1)) * DD + d];
}

__global__ __launch_bounds__(256) void rp2_kernel(
    const float* __restrict__ o2, const float* __restrict__ w,
    const float* __restrict__ bias, float* __restrict__ out)
{
    int b = blockIdx.x, t = threadIdx.x;
    __shared__ float red[256];
    red[t] = o2[b * 256 + t] * w[t];
    __syncthreads();
    for (int s = 128; s > 0; s >>= 1) { if (t < s) red[t] += red[t + s]; __syncthreads(); }
    if (t == 0) out[b] = red[0] + bias[0];
}

// =====================================================================
// launch
// =====================================================================
extern "C" void kernel_launch(void* const* d_in, const int* in_sizes, int n_in,
                              void* d_out, int out_size)
{
    (void)in_sizes; (void)n_in; (void)out_size;
    const float* x_enc     = (const float*)d_in[0];
    const float* conv1_w   = (const float*)d_in[1];
    const float* conv1_b   = (const float*)d_in[2];
    const float* conv2_w   = (const float*)d_in[3];
    const float* conv2_b   = (const float*)d_in[4];
    const float* cnn_ln_g  = (const float*)d_in[5];
    const float* cnn_ln_b  = (const float*)d_in[6];
    const float* proj_w    = (const float*)d_in[7];
    const float* proj_b    = (const float*)d_in[8];
    const float* proj_ln_g = (const float*)d_in[9];
    const float* proj_ln_b = (const float*)d_in[10];
    const float* Wq        = (const float*)d_in[11];
    const float* bq        = (const float*)d_in[12];
    const float* Wk        = (const float*)d_in[13];
    const float* bk        = (const float*)d_in[14];
    const float* Wv        = (const float*)d_in[15];
    const float* bv        = (const float*)d_in[16];
    const float* Wo        = (const float*)d_in[17];
    const float* bo        = (const float*)d_in[18];
    const float* Wff1      = (const float*)d_in[19];
    const float* Wff2      = (const float*)d_in[20];
    const float* rp1_w     = (const float*)d_in[21];
    const float* rp1_b     = (const float*)d_in[22];
    const float* rp_ln_g   = (const float*)d_in[23];
    const float* rp_ln_b   = (const float*)d_in[24];
    const float* rp2_w     = (const float*)d_in[25];
    const float* rp2_b     = (const float*)d_in[26];
    float* out = (float*)d_out;

    float *p_h1, *p_enc, *p_q, *p_k, *p_v, *p_ac, *p_xs, *p_xd, *p_big, *p_rp;
    float *p_emb, *p_final, *p_o1, *p_o2, *p_w, *p_w2t;
    int* p_del;
    cudaGetSymbolAddress((void**)&p_h1,  g_h1);
    cudaGetSymbolAddress((void**)&p_enc, g_enc);
    cudaGetSymbolAddress((void**)&p_q,   g_q);
    cudaGetSymbolAddress((void**)&p_k,   g_k);
    cudaGetSymbolAddress((void**)&p_v,   g_v);
    cudaGetSymbolAddress((void**)&p_ac,  g_ac);
    cudaGetSymbolAddress((void**)&p_xs,  g_xs);
    cudaGetSymbolAddress((void**)&p_xd,  g_xd);
    cudaGetSymbolAddress((void**)&p_big, g_big);
    cudaGetSymbolAddress((void**)&p_rp,  g_rp);
    cudaGetSymbolAddress((void**)&p_del, g_del);
    cudaGetSymbolAddress((void**)&p_w,   g_w);
    cudaGetSymbolAddress((void**)&p_emb, g_emb);
    cudaGetSymbolAddress((void**)&p_final, g_final);
    cudaGetSymbolAddress((void**)&p_o1,  g_o1);
    cudaGetSymbolAddress((void**)&p_o2,  g_o2);
    cudaGetSymbolAddress((void**)&p_w2t, g_w2t);

    const int MBL = BB * LLEN;  // 65536
    const long long SLD = (long long)LLEN * DD;

    // CNN frontend
    conv1_kernel<<<dim3(LLEN, BB), 256>>>(x_enc, conv1_w, conv1_b, p_h1);
    w2t_kernel<<<768, 256>>>(conv2_w, p_w2t);
    tgemm128<1, false, EPI_BIAS | EPI_RELU><<<dim3(2, 8, BB), 256>>>(
        p_h1, p_w2t, conv2_b, nullptr, p_xs, LLEN, DD, 768, SLD, 0, SLD);
    ln256_kernel<<<MBL / 8, 256>>>(p_xs, cnn_ln_g, cnn_ln_b, p_enc, 256, 0);

    for (int i = 0; i < NLAY; i++) {
        const float* Wq_i  = Wq + (long long)i * DD * DD;
        const float* Wk_i  = Wk + (long long)i * DD * DD;
        const float* Wv_i  = Wv + (long long)i * DD * DD;
        const float* Wo_i  = Wo + (long long)i * DD * DD;
        const float* Wf1_i = Wff1 + (long long)i * DFF * DD;
        const float* Wf2_i = Wff2 + (long long)i * DD * DFF;
        const float* bq_i = bq + i * DD;
        const float* bk_i = bk + i * DD;
        const float* bv_i = bv + i * DD;
        const float* bo_i = bo + i * DD;

        // QKV projections (tf32 TC)
        tgemm128<0, false, EPI_BIAS><<<dim3(2, 512, 1), 256>>>(p_enc, Wq_i, bq_i, nullptr, p_q, MBL, DD, DD, 0, 0, 0);
        tgemm128<0, false, EPI_BIAS><<<dim3(2, 512, 1), 256>>>(p_enc, Wk_i, bk_i, nullptr, p_k, MBL, DD, DD, 0, 0, 0);
        tgemm128<0, false, EPI_BIAS><<<dim3(2, 512, 1), 256>>>(p_enc, Wv_i, bv_i, nullptr, p_v, MBL, DD, DD, 0, 0, 0);

        // fused Gram + wrapped-diagonal reduction -> rp[b][tau]
        cudaMemsetAsync(p_rp, 0, (size_t)BB * LLEN * sizeof(float));
        tgemm128<0, true, EPI_GRAM><<<dim3(8, 8, BB), 256>>>(p_q, p_k, nullptr, nullptr, p_rp,
                                                             LLEN, LLEN, DD, SLD, SLD, LLEN);
        topk_kernel<<<BB, 256>>>(p_rp, p_del, p_w);
        agg_kernel<<<dim3(LLEN / 4, BB), 256>>>(p_v, p_del, p_w, p_ac);

        // x = enc + (ac @ Wo + bo)
        tgemm128<0, false, EPI_BIAS | EPI_RES><<<dim3(2, 512, 1), 256>>>(p_ac, Wo_i, bo_i, p_enc, p_xs, MBL, DD, DD, 0, 0, 0);
        decomp_kernel<<<dim3(16, 4, BB), 256>>>(p_xs, p_xd);

        // FFN (tf32 TC)
        tgemm128<0, true, EPI_GELU><<<dim3(8, 512, 1), 256>>>(p_xd, Wf1_i, nullptr, nullptr, p_big, MBL, DFF, DD, 0, 0, 0);
        tgemm128<0, true, EPI_RES><<<dim3(2, 512, 1), 256>>>(p_big, Wf2_i, nullptr, p_xd, p_xs, MBL, DD, DFF, 0, 0, 0);
        decomp_kernel<<<dim3(16, 4, BB), 256>>>(p_xs, p_enc);

        pool_copy_kernel<<<BB, 256>>>(p_enc, p_final, i * DD);
    }

    // input embed head
    sgemm64<EPI_BIAS | EPI_RELU><<<dim3(4, 1), 256>>>(x_enc, proj_w, proj_b, p_emb, BB, HSZ, LLEN * CIN);
    ln256_kernel<<<BB / 8, 256>>>(p_emb, proj_ln_g, proj_ln_b, p_final, NLAY * DD + HSZ, NLAY * DD);

    // regression head
    sgemm64<EPI_BIAS | EPI_RELU><<<dim3(4, 1), 256>>>(p_final, rp1_w, rp1_b, p_o1, BB, HSZ, NLAY * DD + HSZ);
    ln256_kernel<<<BB / 8, 256>>>(p_o1, rp_ln_g, rp_ln_b, p_o2, 256, 0);
    rp2_kernel<<<BB, 256>>>(p_o2, rp2_w, rp2_b, out);
}